// round 5
// baseline (speedup 1.0000x reference)
#include <cuda_runtime.h>
#include <math.h>
#include <stdint.h>
#include <limits.h>

#define T_DIM   4096
#define V_DIM   4096
#define FW      5
#define B_DIM   64
#define S_DIM   512
#define NROWS   (B_DIM * S_DIM)      // 32768
#define VK      (V_DIM * FW)         // 20480
#define TT      256                  // t-tile size
#define NTILES  (T_DIM / TT)         // 16

// Transposed weights: W_T[v*5+k][t], contiguous in t. 335 MB.
__device__ float g_wt[(size_t)VK * T_DIM];

// Per (row, tile) partial: 32 bytes.
struct Part {
    double sd;      // sum of e^l (Kahan fp32 -> double)
    float  w;       // sum of l * e^l
    float  v1, v2;  // top-2 values (v1 >= v2)
    int    i1, i2;  // their t indices
};
__device__ Part g_part[(size_t)NROWS * NTILES];   // [row][tile], 16 MB

// ---------------------------------------------------------------------------
__global__ void k0_zero(float* out) {
    if (threadIdx.x == 0) out[2 * NROWS] = 0.0f;
}

// ---------------------------------------------------------------------------
// kT: W[t][vk] -> W_T[vk][t], 32x32 tiles.
// ---------------------------------------------------------------------------
__global__ __launch_bounds__(256)
void k_transpose(const float* __restrict__ W) {
    __shared__ float tile[32][33];
    const int tx = threadIdx.x & 31;
    const int ty = threadIdx.x >> 5;          // 0..7
    const int t_base  = blockIdx.x * 32;      // 0..127 tiles
    const int vk_base = blockIdx.y * 32;      // 0..639 tiles

    #pragma unroll
    for (int r = 0; r < 32; r += 8)
        tile[ty + r][tx] = W[(size_t)(t_base + ty + r) * VK + vk_base + tx];
    __syncthreads();
    #pragma unroll
    for (int r = 0; r < 32; r += 8)
        g_wt[(size_t)(vk_base + ty + r) * T_DIM + t_base + tx] = tile[tx][ty + r];
}

// ---------------------------------------------------------------------------
// top-2 merge, ties keep smaller index.
// ---------------------------------------------------------------------------
__device__ __forceinline__ void top2_merge(float& v1, int& i1, float& v2, int& i2,
                                           float ov1, int oi1, float ov2, int oi2) {
    float a1, a2; int b1, b2;
    bool firstA = (v1 > ov1) || (v1 == ov1 && i1 <= oi1);
    if (firstA) {
        a1 = v1; b1 = i1;
        bool s = (v2 > ov1) || (v2 == ov1 && i2 <= oi1);
        a2 = s ? v2 : ov1; b2 = s ? i2 : oi1;
    } else {
        a1 = ov1; b1 = oi1;
        bool s = (ov2 > v1) || (ov2 == v1 && oi2 <= i1);
        a2 = s ? ov2 : v1; b2 = s ? oi2 : i1;
    }
    v1 = a1; i1 = b1; v2 = a2; i2 = b2;
}

// ---------------------------------------------------------------------------
// kF: fused logits + per-tile softmax partials.
// grid = NTILES * 1024, TILE-MAJOR: tile = bid>>10, rowblk = bid&1023.
// CTA: 1024 threads = 32 warps; warp = one row (bi, s0+warp); lane covers
// 8 t-values as two float4 chunks. Logits accumulate in registers in the
// reference's exact fp32 order (b + k0 + k1 + k2 + k3 + k4).
// ---------------------------------------------------------------------------
__global__ __launch_bounds__(1024, 1)
void k_fused(const float* __restrict__ b, const int* __restrict__ x) {
    __shared__ int tokvk[36];     // token v*5 for window positions s0-2 .. s0+33

    const int bid  = blockIdx.x;
    const int tile = bid >> 10;
    const int rblk = bid & 1023;
    const int bi   = rblk >> 4;
    const int s0   = (rblk & 15) << 5;
    const int t0   = tile * TT;

    if (threadIdx.x < 36) {
        int p = s0 - 2 + threadIdx.x;
        int v = (p >= 0 && p < S_DIM) ? x[bi * S_DIM + p] : 0;
        tokvk[threadIdx.x] = v * 5;
    }
    __syncthreads();

    const int wrp  = threadIdx.x >> 5;
    const int lane = threadIdx.x & 31;
    const int s    = s0 + wrp;

    // ---- logits: two float4 chunks, t = t0 + lane*4 + 128*jj ----
    float4 a[2];
    #pragma unroll
    for (int jj = 0; jj < 2; jj++) {
        int t = t0 + lane * 4 + 128 * jj;
        a[jj] = __ldg((const float4*)(b + t));
    }
    #pragma unroll
    for (int k = 0; k < FW; k++) {
        int p = s - 2 + k;
        if (p >= 0 && p < S_DIM) {
            const float* Wv = g_wt + (size_t)(tokvk[wrp + k] + k) * T_DIM;
            #pragma unroll
            for (int jj = 0; jj < 2; jj++) {
                int t = t0 + lane * 4 + 128 * jj;
                float4 ww = __ldg((const float4*)(Wv + t));
                a[jj].x += ww.x; a[jj].y += ww.y;
                a[jj].z += ww.z; a[jj].w += ww.w;
            }
        }
    }

    // ---- per-lane stats over 8 values, t ascending ----
    float ssum = 0.0f, scomp = 0.0f, wsum = 0.0f;
    float v1 = -INFINITY, v2 = -INFINITY;
    int   i1 = INT_MAX,   i2 = INT_MAX;

    #pragma unroll
    for (int jj = 0; jj < 2; jj++) {
        float vals[4] = {a[jj].x, a[jj].y, a[jj].z, a[jj].w};
        #pragma unroll
        for (int q = 0; q < 4; q++) {
            float l = vals[q];
            int   t = t0 + lane * 4 + 128 * jj + q;
            float e = __expf(l);
            // Kahan
            float y  = e - scomp;
            float ts = ssum + y;
            scomp = (ts - ssum) - y;
            ssum  = ts;
            wsum = fmaf(l, e, wsum);
            if (l > v1)      { v2 = v1; i2 = i1; v1 = l; i1 = t; }
            else if (l > v2) { v2 = l; i2 = t; }
        }
    }

    // ---- warp reduce ----
    double sd = (double)ssum + (double)scomp;
    #pragma unroll
    for (int off = 16; off > 0; off >>= 1) {
        float ov1 = __shfl_down_sync(0xffffffffu, v1, off);
        int   oi1 = __shfl_down_sync(0xffffffffu, i1, off);
        float ov2 = __shfl_down_sync(0xffffffffu, v2, off);
        int   oi2 = __shfl_down_sync(0xffffffffu, i2, off);
        top2_merge(v1, i1, v2, i2, ov1, oi1, ov2, oi2);
        sd   += __shfl_down_sync(0xffffffffu, sd, off);
        wsum += __shfl_down_sync(0xffffffffu, wsum, off);
    }

    if (lane == 0) {
        int row = bi * S_DIM + s;
        Part p;
        p.sd = sd; p.w = wsum; p.v1 = v1; p.v2 = v2; p.i1 = i1; p.i2 = i2;
        g_part[(size_t)row * NTILES + tile] = p;
    }
}

// ---------------------------------------------------------------------------
// k3: merge NTILES partials per row -> outputs.
// CTA = 512 threads = 16 warps = 16 rows; lane = tile (16 active).
// ---------------------------------------------------------------------------
__global__ __launch_bounds__(512)
void k3_final(float* __restrict__ out) {
    __shared__ float hacc;
    const int wrp  = threadIdx.x >> 5;
    const int lane = threadIdx.x & 31;
    const int row  = blockIdx.x * 16 + wrp;

    if (threadIdx.x == 0) hacc = 0.0f;
    __syncthreads();

    double sd = 0.0;
    float  w  = 0.0f;
    float  v1 = -INFINITY, v2 = -INFINITY;
    int    i1 = INT_MAX,   i2 = INT_MAX;
    if (lane < NTILES) {
        Part p = g_part[(size_t)row * NTILES + lane];
        sd = p.sd; w = p.w; v1 = p.v1; v2 = p.v2; i1 = p.i1; i2 = p.i2;
    }

    #pragma unroll
    for (int off = 16; off > 0; off >>= 1) {
        float ov1 = __shfl_down_sync(0xffffffffu, v1, off);
        int   oi1 = __shfl_down_sync(0xffffffffu, i1, off);
        float ov2 = __shfl_down_sync(0xffffffffu, v2, off);
        int   oi2 = __shfl_down_sync(0xffffffffu, i2, off);
        top2_merge(v1, i1, v2, i2, ov1, oi1, ov2, oi2);
        sd += __shfl_down_sync(0xffffffffu, sd, off);
        w  += __shfl_down_sync(0xffffffffu, w, off);
    }

    if (lane == 0) {
        float  m   = v1;                      // exact row max
        double ls0 = log(sd);                 // ln(sum e^l)
        float  lse_f = (float)(ls0 - (double)m);
        float  key0  = 0.0f - lse_f;          // rounded key of the max

        // tie-aware argmax: candidates = entries whose rounded key equals key0
        int cand = INT_MAX;
        if (((v1 - m) - lse_f) == key0) cand = min(cand, i1);
        if (((v2 - m) - lse_f) == key0) cand = min(cand, i2);

        out[row]         = (float)cand;
        out[NROWS + row] = -lse_f;
        float H = (float)ls0 - (float)((double)w / sd);
        atomicAdd(&hacc, H * (1.0f / ((float)NROWS * (float)T_DIM)));
    }
    __syncthreads();
    if (threadIdx.x == 0) atomicAdd(out + 2 * NROWS, hacc);
}

// ---------------------------------------------------------------------------
extern "C" void kernel_launch(void* const* d_in, const int* in_sizes, int n_in,
                              void* d_out, int out_size) {
    const float* W = nullptr;
    const float* b = nullptr;
    const int*   x = nullptr;
    for (int i = 0; i < n_in; i++) {
        if (in_sizes[i] == T_DIM * V_DIM * FW) W = (const float*)d_in[i];
        else if (in_sizes[i] == T_DIM)         b = (const float*)d_in[i];
        else if (in_sizes[i] == NROWS)         x = (const int*)d_in[i];
    }
    float* out = (float*)d_out;

    // 4 launches per call -> profiled launch #7 = call 2's k_fused.
    k0_zero<<<1, 32>>>(out);
    k_transpose<<<dim3(T_DIM / 32, VK / 32), 256>>>(W);
    k_fused<<<NTILES * 1024, 1024>>>(b, x);
    k3_final<<<NROWS / 16, 512>>>(out);
}

// round 6
// speedup vs baseline: 1.7855x; 1.7855x over previous
#include <cuda_runtime.h>
#include <math.h>
#include <stdint.h>
#include <limits.h>

#define T_DIM   4096
#define V_DIM   4096
#define FW      5
#define B_DIM   64
#define S_DIM   512
#define NROWS   (B_DIM * S_DIM)      // 32768
#define VK      (V_DIM * FW)         // 20480
#define TT      512                  // t-tile size
#define NTILES  (T_DIM / TT)         // 8
#define RPB     16                   // rows per kF CTA

// Transposed weights: W_T[v*5+k][t], contiguous in t. 335 MB.
__device__ float g_wt[(size_t)VK * T_DIM];

// Per (row, tile) partial: 32 bytes (16B-aligned for LDG.128).
struct __align__(16) Part {
    float s;        // sum of e^l (fp32 pairwise)
    float w;        // sum of l * e^l
    float v1, v2;   // top-2 values (v1 >= v2)
    int   i1, i2;   // their t indices
    int   pad0, pad1;
};
__device__ Part g_part[(size_t)NROWS * NTILES];   // [row][tile], 8 MB

// ---------------------------------------------------------------------------
__global__ void k0_zero(float* out) {
    if (threadIdx.x == 0) out[2 * NROWS] = 0.0f;
}

// ---------------------------------------------------------------------------
// kT: W[t][vk] -> W_T[vk][t], 32x32 tiles via smem.
// ---------------------------------------------------------------------------
__global__ __launch_bounds__(256)
void k_transpose(const float* __restrict__ W) {
    __shared__ float tile[32][33];
    const int tx = threadIdx.x & 31;
    const int ty = threadIdx.x >> 5;          // 0..7
    const int t_base  = blockIdx.x * 32;
    const int vk_base = blockIdx.y * 32;

    #pragma unroll
    for (int r = 0; r < 32; r += 8)
        tile[ty + r][tx] = W[(size_t)(t_base + ty + r) * VK + vk_base + tx];
    __syncthreads();
    #pragma unroll
    for (int r = 0; r < 32; r += 8)
        g_wt[(size_t)(vk_base + ty + r) * T_DIM + t_base + tx] = tile[tx][ty + r];
}

// ---------------------------------------------------------------------------
// top-2 merge, ties keep smaller index.
// ---------------------------------------------------------------------------
__device__ __forceinline__ void top2_merge(float& v1, int& i1, float& v2, int& i2,
                                           float ov1, int oi1, float ov2, int oi2) {
    float a1, a2; int b1, b2;
    bool firstA = (v1 > ov1) || (v1 == ov1 && i1 <= oi1);
    if (firstA) {
        a1 = v1; b1 = i1;
        bool s = (v2 > ov1) || (v2 == ov1 && i2 <= oi1);
        a2 = s ? v2 : ov1; b2 = s ? i2 : oi1;
    } else {
        a1 = ov1; b1 = oi1;
        bool s = (ov2 > v1) || (ov2 == v1 && oi2 <= i1);
        a2 = s ? ov2 : v1; b2 = s ? oi2 : i1;
    }
    v1 = a1; i1 = b1; v2 = a2; i2 = b2;
}

// ---------------------------------------------------------------------------
// kF: fused logits + per-tile softmax partials, all fp32.
// grid = NTILES * (NROWS/RPB), TILE-MAJOR. CTA: 512 threads = 16 warps;
// warp = one row (bi, s0+warp); lane covers 16 t's as four float4 chunks.
// Logits accumulate in registers in the reference's exact fp32 order
// (b + k0 + k1 + k2 + k3 + k4).
// ---------------------------------------------------------------------------
__global__ __launch_bounds__(512)
void k_fused(const float* __restrict__ b, const int* __restrict__ x) {
    __shared__ int tokvk[RPB + 4];   // token v*5 for positions s0-2 .. s0+RPB+1

    const int bid  = blockIdx.x;
    const int tile = bid / (NROWS / RPB);
    const int rblk = bid % (NROWS / RPB);
    const int bi   = rblk / (S_DIM / RPB);
    const int s0   = (rblk % (S_DIM / RPB)) * RPB;
    const int t0   = tile * TT;

    if (threadIdx.x < RPB + 4) {
        int p = s0 - 2 + threadIdx.x;
        int v = (p >= 0 && p < S_DIM) ? x[bi * S_DIM + p] : 0;
        tokvk[threadIdx.x] = v * 5;
    }
    __syncthreads();

    const int wrp  = threadIdx.x >> 5;
    const int lane = threadIdx.x & 31;
    const int s    = s0 + wrp;

    // ---- logits: four float4 chunks, t = t0 + 128*jj + lane*4 ----
    float4 a[4];
    #pragma unroll
    for (int jj = 0; jj < 4; jj++)
        a[jj] = __ldg((const float4*)(b + t0 + 128 * jj + lane * 4));

    #pragma unroll
    for (int k = 0; k < FW; k++) {
        int p = s - 2 + k;
        if (p >= 0 && p < S_DIM) {
            const float* Wv = g_wt + (size_t)(tokvk[wrp + k] + k) * T_DIM + t0;
            #pragma unroll
            for (int jj = 0; jj < 4; jj++) {
                float4 ww = __ldg((const float4*)(Wv + 128 * jj + lane * 4));
                a[jj].x += ww.x; a[jj].y += ww.y;
                a[jj].z += ww.z; a[jj].w += ww.w;
            }
        }
    }

    // ---- per-lane stats over 16 values ----
    float csum[4];
    float wsum0 = 0.0f, wsum1 = 0.0f;
    float v1 = -INFINITY, v2 = -INFINITY;
    int   i1 = INT_MAX,   i2 = INT_MAX;

    #pragma unroll
    for (int jj = 0; jj < 4; jj++) {
        float e0 = __expf(a[jj].x);
        float e1 = __expf(a[jj].y);
        float e2 = __expf(a[jj].z);
        float e3 = __expf(a[jj].w);
        csum[jj] = (e0 + e1) + (e2 + e3);
        wsum0 = fmaf(a[jj].x, e0, wsum0);
        wsum1 = fmaf(a[jj].y, e1, wsum1);
        wsum0 = fmaf(a[jj].z, e2, wsum0);
        wsum1 = fmaf(a[jj].w, e3, wsum1);
        float vals[4] = {a[jj].x, a[jj].y, a[jj].z, a[jj].w};
        #pragma unroll
        for (int q = 0; q < 4; q++) {
            float l = vals[q];
            int   t = t0 + 128 * jj + lane * 4 + q;
            if (l > v1)      { v2 = v1; i2 = i1; v1 = l; i1 = t; }
            else if (l > v2) { v2 = l; i2 = t; }
        }
    }
    float ssum = (csum[0] + csum[1]) + (csum[2] + csum[3]);
    float wsum = wsum0 + wsum1;

    // ---- warp reduce ----
    #pragma unroll
    for (int off = 16; off > 0; off >>= 1) {
        float ov1 = __shfl_down_sync(0xffffffffu, v1, off);
        int   oi1 = __shfl_down_sync(0xffffffffu, i1, off);
        float ov2 = __shfl_down_sync(0xffffffffu, v2, off);
        int   oi2 = __shfl_down_sync(0xffffffffu, i2, off);
        top2_merge(v1, i1, v2, i2, ov1, oi1, ov2, oi2);
        ssum += __shfl_down_sync(0xffffffffu, ssum, off);
        wsum += __shfl_down_sync(0xffffffffu, wsum, off);
    }

    if (lane == 0) {
        int row = bi * S_DIM + s;
        Part p;
        p.s = ssum; p.w = wsum; p.v1 = v1; p.v2 = v2; p.i1 = i1; p.i2 = i2;
        p.pad0 = 0; p.pad1 = 0;
        g_part[(size_t)row * NTILES + tile] = p;
    }
}

// ---------------------------------------------------------------------------
// k3: merge NTILES=8 partials per row -> outputs. All fp32.
// CTA = 256 threads = 8 warps = 8 rows; lane = tile (8 active).
// ---------------------------------------------------------------------------
__global__ __launch_bounds__(256)
void k3_final(float* __restrict__ out) {
    __shared__ float hacc;
    const int wrp  = threadIdx.x >> 5;
    const int lane = threadIdx.x & 31;
    const int row  = blockIdx.x * 8 + wrp;

    if (threadIdx.x == 0) hacc = 0.0f;
    __syncthreads();

    float s = 0.0f, w = 0.0f;
    float v1 = -INFINITY, v2 = -INFINITY;
    int   i1 = INT_MAX,   i2 = INT_MAX;
    if (lane < NTILES) {
        Part p = g_part[(size_t)row * NTILES + lane];
        s = p.s; w = p.w; v1 = p.v1; v2 = p.v2; i1 = p.i1; i2 = p.i2;
    }

    #pragma unroll
    for (int off = 4; off > 0; off >>= 1) {
        float ov1 = __shfl_down_sync(0xffffffffu, v1, off);
        int   oi1 = __shfl_down_sync(0xffffffffu, i1, off);
        float ov2 = __shfl_down_sync(0xffffffffu, v2, off);
        int   oi2 = __shfl_down_sync(0xffffffffu, i2, off);
        top2_merge(v1, i1, v2, i2, ov1, oi1, ov2, oi2);
        s += __shfl_down_sync(0xffffffffu, s, off);
        w += __shfl_down_sync(0xffffffffu, w, off);
    }

    if (lane == 0) {
        float m     = v1;                  // exact row max
        float ls0   = __logf(s);           // ln(sum e^l), fp32 grid point
        float lse_f = ls0 - m;             // ~ ref's log(sum e^{l-m})
        float key0  = 0.0f - lse_f;        // rounded key of the max

        // tie-aware argmax: first index whose rounded key equals the max key
        int cand = INT_MAX;
        if (((v1 - m) - lse_f) == key0) cand = min(cand, i1);
        if (((v2 - m) - lse_f) == key0) cand = min(cand, i2);

        out[row]         = (float)cand;
        out[NROWS + row] = -lse_f;
        float H = ls0 - w / s;
        atomicAdd(&hacc, H * (1.0f / ((float)NROWS * (float)T_DIM)));
    }
    __syncthreads();
    if (threadIdx.x == 0) atomicAdd(out + 2 * NROWS, hacc);
}

// ---------------------------------------------------------------------------
extern "C" void kernel_launch(void* const* d_in, const int* in_sizes, int n_in,
                              void* d_out, int out_size) {
    const float* W = nullptr;
    const float* b = nullptr;
    const int*   x = nullptr;
    for (int i = 0; i < n_in; i++) {
        if (in_sizes[i] == T_DIM * V_DIM * FW) W = (const float*)d_in[i];
        else if (in_sizes[i] == T_DIM)         b = (const float*)d_in[i];
        else if (in_sizes[i] == NROWS)         x = (const int*)d_in[i];
    }
    float* out = (float*)d_out;

    k0_zero<<<1, 32>>>(out);
    k_transpose<<<dim3(T_DIM / 32, VK / 32), 256>>>(W);
    k_fused<<<NTILES * (NROWS / RPB), 512>>>(b, x);
    k3_final<<<NROWS / 8, 256>>>(out);
}

// round 7
// speedup vs baseline: 2.0505x; 1.1484x over previous
#include <cuda_runtime.h>
#include <math.h>
#include <stdint.h>
#include <limits.h>

#define T_DIM   4096
#define V_DIM   4096
#define FW      5
#define B_DIM   64
#define S_DIM   512
#define NROWS   (B_DIM * S_DIM)      // 32768
#define VK      (V_DIM * FW)         // 20480
#define TT      512                  // t-tile size
#define NTILES  (T_DIM / TT)         // 8
#define RPB     16                   // rows per kF CTA

typedef unsigned long long u64;

// Transposed weights: W_T[v*5+k][t], contiguous in t. 335 MB.
__device__ float g_wt[(size_t)VK * T_DIM];

// Per (row, tile) partial: 32 bytes (16B-aligned for LDG.128).
struct __align__(16) Part {
    float s;        // sum of e^l (fp32 pairwise)
    float w;        // sum of l * e^l
    float v1, v2;   // top-2 values (v1 >= v2)
    int   i1, i2;   // their t indices
    int   pad0, pad1;
};
__device__ Part g_part[(size_t)NROWS * NTILES];   // [row][tile], 8 MB

// packed f32x2 add: per-component IEEE RN, bitwise == two scalar FADDs
__device__ __forceinline__ void add2(u64& acc, u64 v) {
    asm("add.rn.f32x2 %0, %1, %2;" : "=l"(acc) : "l"(acc), "l"(v));
}
__device__ __forceinline__ float2 u2f(u64 v) {
    float2 f;
    asm("mov.b64 {%0, %1}, %2;" : "=f"(f.x), "=f"(f.y) : "l"(v));
    return f;
}

// ---------------------------------------------------------------------------
__global__ void k0_zero(float* out) {
    if (threadIdx.x == 0) out[2 * NROWS] = 0.0f;
}

// ---------------------------------------------------------------------------
// kT: W[t][vk] -> W_T[vk][t], 32x32 tiles via smem.
// ---------------------------------------------------------------------------
__global__ __launch_bounds__(256)
void k_transpose(const float* __restrict__ W) {
    __shared__ float tile[32][33];
    const int tx = threadIdx.x & 31;
    const int ty = threadIdx.x >> 5;          // 0..7
    const int t_base  = blockIdx.x * 32;
    const int vk_base = blockIdx.y * 32;

    #pragma unroll
    for (int r = 0; r < 32; r += 8)
        tile[ty + r][tx] = W[(size_t)(t_base + ty + r) * VK + vk_base + tx];
    __syncthreads();
    #pragma unroll
    for (int r = 0; r < 32; r += 8)
        g_wt[(size_t)(vk_base + ty + r) * T_DIM + t_base + tx] = tile[tx][ty + r];
}

// ---------------------------------------------------------------------------
// top-2 merge, ties keep smaller index.
// ---------------------------------------------------------------------------
__device__ __forceinline__ void top2_merge(float& v1, int& i1, float& v2, int& i2,
                                           float ov1, int oi1, float ov2, int oi2) {
    float a1, a2; int b1, b2;
    bool firstA = (v1 > ov1) || (v1 == ov1 && i1 <= oi1);
    if (firstA) {
        a1 = v1; b1 = i1;
        bool s = (v2 > ov1) || (v2 == ov1 && i2 <= oi1);
        a2 = s ? v2 : ov1; b2 = s ? i2 : oi1;
    } else {
        a1 = ov1; b1 = oi1;
        bool s = (ov2 > v1) || (ov2 == v1 && oi2 <= i1);
        a2 = s ? ov2 : v1; b2 = s ? oi2 : i1;
    }
    v1 = a1; i1 = b1; v2 = a2; i2 = b2;
}

// ---------------------------------------------------------------------------
// kF: fused logits + per-tile softmax partials, all fp32, packed-f32x2 adds.
// grid = NTILES * (NROWS/RPB), TILE-MAJOR. CTA: 512 threads = 16 warps;
// warp = one row (bi, s0+warp); lane covers 16 t's as four 16B chunks.
// Accumulation order is the reference's exact fp32 order per component
// (b + k0 + k1 + k2 + k3 + k4).
// ---------------------------------------------------------------------------
__global__ __launch_bounds__(512, 3)
void k_fused(const float* __restrict__ b, const int* __restrict__ x) {
    __shared__ int tokvk[RPB + 4];   // token v*5 for positions s0-2 .. s0+RPB+1

    const int bid  = blockIdx.x;
    const int tile = bid / (NROWS / RPB);
    const int rblk = bid % (NROWS / RPB);
    const int bi   = rblk / (S_DIM / RPB);
    const int s0   = (rblk % (S_DIM / RPB)) * RPB;
    const int t0   = tile * TT;

    if (threadIdx.x < RPB + 4) {
        int p = s0 - 2 + threadIdx.x;
        int v = (p >= 0 && p < S_DIM) ? x[bi * S_DIM + p] : 0;
        tokvk[threadIdx.x] = v * 5;
    }
    __syncthreads();

    const int wrp  = threadIdx.x >> 5;
    const int lane = threadIdx.x & 31;
    const int s    = s0 + wrp;

    // ---- logits: 4 chunks of 4 floats as 2 packed f32x2 each ----
    u64 acc[8];
    #pragma unroll
    for (int jj = 0; jj < 4; jj++) {
        ulonglong2 bb = __ldg((const ulonglong2*)(b + t0 + 128 * jj + lane * 4));
        acc[2 * jj]     = bb.x;
        acc[2 * jj + 1] = bb.y;
    }

    #pragma unroll
    for (int k = 0; k < FW; k++) {
        int p = s - 2 + k;
        if (p >= 0 && p < S_DIM) {
            const float* Wv = g_wt + (size_t)(tokvk[wrp + k] + k) * T_DIM + t0;
            #pragma unroll
            for (int jj = 0; jj < 4; jj++) {
                ulonglong2 ww = __ldg((const ulonglong2*)(Wv + 128 * jj + lane * 4));
                add2(acc[2 * jj],     ww.x);
                add2(acc[2 * jj + 1], ww.y);
            }
        }
    }

    // ---- per-lane stats over 16 values ----
    float csum[4];
    float wsum0 = 0.0f, wsum1 = 0.0f;
    float v1 = -INFINITY, v2 = -INFINITY;
    int   i1 = INT_MAX,   i2 = INT_MAX;

    #pragma unroll
    for (int jj = 0; jj < 4; jj++) {
        float2 lo = u2f(acc[2 * jj]);
        float2 hi = u2f(acc[2 * jj + 1]);
        float e0 = __expf(lo.x);
        float e1 = __expf(lo.y);
        float e2 = __expf(hi.x);
        float e3 = __expf(hi.y);
        csum[jj] = (e0 + e1) + (e2 + e3);
        wsum0 = fmaf(lo.x, e0, wsum0);
        wsum1 = fmaf(lo.y, e1, wsum1);
        wsum0 = fmaf(hi.x, e2, wsum0);
        wsum1 = fmaf(hi.y, e3, wsum1);
        float vals[4] = {lo.x, lo.y, hi.x, hi.y};
        #pragma unroll
        for (int q = 0; q < 4; q++) {
            float l = vals[q];
            int   t = t0 + 128 * jj + lane * 4 + q;
            if (l > v1)      { v2 = v1; i2 = i1; v1 = l; i1 = t; }
            else if (l > v2) { v2 = l; i2 = t; }
        }
    }
    float ssum = (csum[0] + csum[1]) + (csum[2] + csum[3]);
    float wsum = wsum0 + wsum1;

    // ---- warp reduce ----
    #pragma unroll
    for (int off = 16; off > 0; off >>= 1) {
        float ov1 = __shfl_down_sync(0xffffffffu, v1, off);
        int   oi1 = __shfl_down_sync(0xffffffffu, i1, off);
        float ov2 = __shfl_down_sync(0xffffffffu, v2, off);
        int   oi2 = __shfl_down_sync(0xffffffffu, i2, off);
        top2_merge(v1, i1, v2, i2, ov1, oi1, ov2, oi2);
        ssum += __shfl_down_sync(0xffffffffu, ssum, off);
        wsum += __shfl_down_sync(0xffffffffu, wsum, off);
    }

    if (lane == 0) {
        int row = bi * S_DIM + s;
        Part p;
        p.s = ssum; p.w = wsum; p.v1 = v1; p.v2 = v2; p.i1 = i1; p.i2 = i2;
        p.pad0 = 0; p.pad1 = 0;
        g_part[(size_t)row * NTILES + tile] = p;
    }
}

// ---------------------------------------------------------------------------
// k3: merge NTILES=8 partials per row -> outputs. All fp32.
// CTA = 256 threads = 8 warps = 8 rows; lane = tile (8 active).
// ---------------------------------------------------------------------------
__global__ __launch_bounds__(256)
void k3_final(float* __restrict__ out) {
    __shared__ float hacc;
    const int wrp  = threadIdx.x >> 5;
    const int lane = threadIdx.x & 31;
    const int row  = blockIdx.x * 8 + wrp;

    if (threadIdx.x == 0) hacc = 0.0f;
    __syncthreads();

    float s = 0.0f, w = 0.0f;
    float v1 = -INFINITY, v2 = -INFINITY;
    int   i1 = INT_MAX,   i2 = INT_MAX;
    if (lane < NTILES) {
        Part p = g_part[(size_t)row * NTILES + lane];
        s = p.s; w = p.w; v1 = p.v1; v2 = p.v2; i1 = p.i1; i2 = p.i2;
    }

    #pragma unroll
    for (int off = 4; off > 0; off >>= 1) {
        float ov1 = __shfl_down_sync(0xffffffffu, v1, off);
        int   oi1 = __shfl_down_sync(0xffffffffu, i1, off);
        float ov2 = __shfl_down_sync(0xffffffffu, v2, off);
        int   oi2 = __shfl_down_sync(0xffffffffu, i2, off);
        top2_merge(v1, i1, v2, i2, ov1, oi1, ov2, oi2);
        s += __shfl_down_sync(0xffffffffu, s, off);
        w += __shfl_down_sync(0xffffffffu, w, off);
    }

    if (lane == 0) {
        float m     = v1;                  // exact row max
        float ls0   = __logf(s);           // ln(sum e^l), fp32 grid point
        float lse_f = ls0 - m;             // ~ ref's log(sum e^{l-m})
        float key0  = 0.0f - lse_f;        // rounded key of the max

        // tie-aware argmax: first index whose rounded key equals the max key
        int cand = INT_MAX;
        if (((v1 - m) - lse_f) == key0) cand = min(cand, i1);
        if (((v2 - m) - lse_f) == key0) cand = min(cand, i2);

        out[row]         = (float)cand;
        out[NROWS + row] = -lse_f;
        float H = ls0 - w / s;
        atomicAdd(&hacc, H * (1.0f / ((float)NROWS * (float)T_DIM)));
    }
    __syncthreads();
    if (threadIdx.x == 0) atomicAdd(out + 2 * NROWS, hacc);
}

// ---------------------------------------------------------------------------
extern "C" void kernel_launch(void* const* d_in, const int* in_sizes, int n_in,
                              void* d_out, int out_size) {
    const float* W = nullptr;
    const float* b = nullptr;
    const int*   x = nullptr;
    for (int i = 0; i < n_in; i++) {
        if (in_sizes[i] == T_DIM * V_DIM * FW) W = (const float*)d_in[i];
        else if (in_sizes[i] == T_DIM)         b = (const float*)d_in[i];
        else if (in_sizes[i] == NROWS)         x = (const int*)d_in[i];
    }
    float* out = (float*)d_out;

    k0_zero<<<1, 32>>>(out);
    k_transpose<<<dim3(T_DIM / 32, VK / 32), 256>>>(W);
    k_fused<<<NTILES * (NROWS / RPB), 512>>>(b, x);
    k3_final<<<NROWS / 8, 256>>>(out);
}